// round 16
// baseline (speedup 1.0000x reference)
#include <cuda_runtime.h>

#define S_LEN 16384
#define HL 48
#define HR 24

typedef unsigned long long u64;

__device__ u64   g_xw0[(size_t)S_LEN * 96];       // permuted, PRE-SCALED packed gate pairs
__device__ u64   g_xwb[4][(size_t)S_LEN * 96];
__device__ float g_hb[5][(size_t)S_LEN * HL];
__device__ float g_r0[(size_t)S_LEN * HR];
__device__ int   g_cnt[16 * 32];                  // padded: one counter per 128B

#define BARS(id, cnt) asm volatile("bar.sync %0, %1;" :: "r"(id), "r"(cnt) : "memory")

__device__ __forceinline__ int imin(int a, int b) { return a < b ? a : b; }

__device__ __forceinline__ u64 pack2(float x, float y) {
    u64 r; asm("mov.b64 %0, {%1, %2};" : "=l"(r) : "f"(x), "f"(y)); return r;
}
__device__ __forceinline__ void unpack2(u64 v, float &x, float &y) {
    asm("mov.b64 {%0, %1}, %2;" : "=f"(x), "=f"(y) : "l"(v));
}
__device__ __forceinline__ u64 ffma2(u64 a, u64 b, u64 c) {
    u64 d; asm("fma.rn.f32x2 %0, %1, %2, %3;" : "=l"(d) : "l"(a), "l"(b), "l"(c)); return d;
}
__device__ __forceinline__ u64 add2(u64 a, u64 b) {
    u64 d; asm("add.rn.f32x2 %0, %1, %2;" : "=l"(d) : "l"(a), "l"(b)); return d;
}
__device__ __forceinline__ int ld_acq(const int *p) {
    int v; asm volatile("ld.acquire.gpu.global.b32 %0, [%1];" : "=r"(v) : "l"(p)); return v;
}
__device__ __forceinline__ void st_rel(int *p, int v) {
    asm volatile("st.release.gpu.global.b32 [%0], %1;" :: "l"(p), "r"(v));
}
__device__ __forceinline__ float tanhap(float x) {
    float y; asm("tanh.approx.f32 %0, %1;" : "=f"(y) : "f"(x)); return y;
}
// gate-pair permutation: thread p owns rows (rX, rY) of the 192-row gate matrix.
__device__ __forceinline__ void rowpair(int p, int &rX, int &rY) {
    int w = p >> 5, l = p & 31;
    int m = 16 * w + (l & 15);
    if (l < 16) { rX = m;      rY = 96 + m;  }
    else        { rX = 48 + m; rY = 144 + m; }
}
// pre-scale per gate row: sigmoid rows (i,f,o) carry 0.5; tanh rows (g) carry 1.0
__device__ __forceinline__ float rowscale(int r) {
    return (r >= 96 && r < 144) ? 1.f : 0.5f;
}

// ------------------- shared memory overlays (dynamic) -------------------
struct LstmSmem { u64 xw[64][96]; float hb[2][48]; };
struct XwSmem   { float h[64][48]; };
struct Rnn0Smem { float hin[64][48]; float xw[16][24]; float hb[2][24]; };
struct Rnn1Smem { float rin[64][24]; float xw[16][24]; float hb[2][24]; };
#define PIPE_SMEM_BYTES (sizeof(LstmSmem) + 128)

// ---------------- front: fc1 -> relu -> fc2 -> relu -> permuted scaled xw0 ----------------
__global__ void __launch_bounds__(128) front_kernel(
    const float* __restrict__ x,
    const float* __restrict__ fc1W, const float* __restrict__ fc1b,
    const float* __restrict__ fc2W, const float* __restrict__ fc2b,
    const float* __restrict__ Wih0,
    const float* __restrict__ bih0, const float* __restrict__ bhh0)
{
    __shared__ float s1W[120], s1b[20], s2W[400], s2b[20], s0W[3840], s0b[192];
    const int tid = threadIdx.x;
    for (int i = tid; i < 120; i += 128) s1W[i] = fc1W[i];
    for (int i = tid; i < 400; i += 128) s2W[i] = fc2W[i];
    for (int i = tid; i < 3840; i += 128) s0W[i] = Wih0[i] * rowscale(i / 20);
    for (int i = tid; i < 192; i += 128) s0b[i] = (bih0[i] + bhh0[i]) * rowscale(i);
    if (tid < 20) { s1b[tid] = fc1b[tid]; s2b[tid] = fc2b[tid]; }
    if (blockIdx.x == 0 && tid < 16) g_cnt[tid * 32] = 0;
    __syncthreads();

    const int t = blockIdx.x * 128 + tid;
    float xin[6];
#pragma unroll
    for (int i = 0; i < 6; i++) xin[i] = x[t * 6 + i];
    float h1[20];
#pragma unroll
    for (int j = 0; j < 20; j++) {
        float s = s1b[j];
#pragma unroll
        for (int i = 0; i < 6; i++) s += xin[i] * s1W[j * 6 + i];
        h1[j] = fmaxf(s, 0.f);
    }
    float h2[20];
#pragma unroll
    for (int j = 0; j < 20; j++) {
        float s = s2b[j];
#pragma unroll
        for (int i = 0; i < 20; i++) s += h1[i] * s2W[j * 20 + i];
        h2[j] = fmaxf(s, 0.f);
    }
    for (int p = 0; p < 96; p++) {
        int rX, rY; rowpair(p, rX, rY);
        float sX = s0b[rX], sY = s0b[rY];
#pragma unroll
        for (int k = 0; k < 20; k++) {
            float hv = h2[k];
            sX += hv * s0W[rX * 20 + k];
            sY += hv * s0W[rY * 20 + k];
        }
        g_xw0[(size_t)t * 96 + p] = pack2(sX, sY);
    }
}

// ---------------- LSTM recurrence: slack loader (ring 64), shfl gate exchange ----------------
__device__ void lstm_rec(unsigned char* smem_raw,
                         const float* __restrict__ Whh, const u64* __restrict__ xwsrc,
                         const int* upcnt, float* __restrict__ hout, int* mycnt)
{
    LstmSmem* sm = reinterpret_cast<LstmSmem*>(smem_raw);
    const int tid = threadIdx.x;

    if (tid < 96) {
        u64 wX[24], wY[24];
        int rX, rY; rowpair(tid, rX, rY);
        const float scX = rowscale(rX), scY = rowscale(rY);
        const float* r0 = Whh + rX * HL;
        const float* r1 = Whh + rY * HL;
#pragma unroll
        for (int j = 0; j < 24; j++) {
            wX[j] = pack2(r0[2 * j] * scX, r0[2 * j + 1] * scX);
            wY[j] = pack2(r1[2 * j] * scY, r1[2 * j + 1] * scY);
        }
        const int m = 16 * (tid >> 5) + (tid & 15);
        const bool isA = (tid & 31) < 16;
        const float avm = isA ? 1.f : 0.5f;
        const float avb = isA ? 0.f : 0.5f;
        float c = 0.f;
        if (tid < 48) sm->hb[0][tid] = 0.f;
        __syncthreads();

        u64 xw_cur = sm->xw[0][tid];
        for (int t = 0; t < S_LEN; t++) {
            float xwX, xwY; unpack2(xw_cur, xwX, xwY);
            const ulonglong2* hd2 = (const ulonglong2*)sm->hb[t & 1];
            // fold xw into accumulator init (off-chain) instead of post-reduce add
            u64 aX0 = pack2(xwX, 0.f), aX1 = 0, aY0 = pack2(xwY, 0.f), aY1 = 0;
#pragma unroll
            for (int j = 0; j < 12; j++) {
                ulonglong2 hh = hd2[j];
                aX0 = ffma2(hh.x, wX[2 * j], aX0);
                aX1 = ffma2(hh.y, wX[2 * j + 1], aX1);
                aY0 = ffma2(hh.x, wY[2 * j], aY0);
                aY1 = ffma2(hh.y, wY[2 * j + 1], aY1);
            }
            aX0 = add2(aX0, aX1); aY0 = add2(aY0, aY1);
            float x0, x1, y0, y1;
            unpack2(aX0, x0, x1); unpack2(aY0, y0, y1);
            float gx = x0 + x1;
            float gy = y0 + y1;
            float ax = fmaf(0.5f, tanhap(gx), 0.5f);   // sigmoid (i / f); 0.5 folded into W
            float ay = fmaf(avm, tanhap(gy), avb);     // A: tanh(g)  B: sigmoid(o)
            float fv = __shfl_down_sync(0xffffffffu, ax, 16);
            float ov = __shfl_down_sync(0xffffffffu, ay, 16);
            if (isA) {
                c = fmaf(fv, c, ax * ay);
                float h = ov * tanhap(c);
                sm->hb[(t + 1) & 1][m] = h;
                hout[(size_t)t * HL + m] = h;
            }
            if ((t & 15) != 15) {
                u64 xw_nxt = sm->xw[(t + 1) & 63][tid];   // row t+1 < W+32: filled
                BARS(2, 96);
                xw_cur = xw_nxt;
            } else {
                BARS(1, 128);
                xw_cur = sm->xw[(t + 1) & 63][tid];       // first row of next window
            }
        }
    } else {
        const int lane = tid - 96;
        int avail = 0, filled = 0;
        if (upcnt) { while (avail < 48) avail = ld_acq(upcnt); }
        else avail = S_LEN;
        {
            int lim = imin(avail, 64);
            for (int r = 0; r < lim; r++) {
                const u64* src = xwsrc + (size_t)r * 96;
                u64* dst = sm->xw[r & 63];
                dst[lane] = src[lane]; dst[32 + lane] = src[32 + lane]; dst[64 + lane] = src[64 + lane];
            }
            filled = lim;
        }
        __syncthreads();

        for (int W = 0; W < S_LEN; W += 16) {
            // finer-grained publish: half-window first (progress the downstream saw at W)
            if (lane == 0 && mycnt) st_rel(mycnt, W + 8);
            int must = imin(W + 48, S_LEN);
            if (filled < must) {
                if (upcnt) { while (avail < must) avail = ld_acq(upcnt); }
                else avail = S_LEN;
            } else if (upcnt && filled < S_LEN) {
                int a = ld_acq(upcnt); if (a > avail) avail = a;   // opportunistic refresh
            }
            int lim = imin(imin(W + 64, S_LEN), avail);
            for (int r = filled; r < lim; r++) {
                const u64* src = xwsrc + (size_t)r * 96;
                u64* dst = sm->xw[r & 63];
                dst[lane] = src[lane]; dst[32 + lane] = src[32 + lane]; dst[64 + lane] = src[64 + lane];
            }
            filled = lim;
            BARS(1, 128);
            if (lane == 0 && mycnt) st_rel(mycnt, W + 16);
        }
    }
}

// ---------------- feedforward xw stage (LSTM layers 1..4), slack loader ----------------
__device__ void xw_stage(unsigned char* smem_raw,
                         const float* __restrict__ Wih, const float* __restrict__ bih,
                         const float* __restrict__ bhh, const float* __restrict__ hin,
                         const int* upcnt, u64* __restrict__ xwout, int* mycnt)
{
    XwSmem* sm = reinterpret_cast<XwSmem*>(smem_raw);
    const int tid = threadIdx.x;

    if (tid < 96) {
        u64 wX[24], wY[24];
        int rX, rY; rowpair(tid, rX, rY);
        const float scX = rowscale(rX), scY = rowscale(rY);
        const float* r0 = Wih + rX * HL;
        const float* r1 = Wih + rY * HL;
#pragma unroll
        for (int j = 0; j < 24; j++) {
            wX[j] = pack2(r0[2 * j] * scX, r0[2 * j + 1] * scX);
            wY[j] = pack2(r1[2 * j] * scY, r1[2 * j + 1] * scY);
        }
        const float biasX = (bih[rX] + bhh[rX]) * scX;
        const float biasY = (bih[rY] + bhh[rY]) * scY;
        const u64 binitX = pack2(biasX, 0.f);
        const u64 binitY = pack2(biasY, 0.f);
        __syncthreads();

        for (int W = 0; W < S_LEN; W += 16) {
#pragma unroll 4
            for (int s = 0; s < 16; s++) {
                int t = W + s;
                const ulonglong2* hd2 = (const ulonglong2*)sm->h[t & 63];
                u64 aX0 = binitX, aX1 = 0, aY0 = binitY, aY1 = 0;
#pragma unroll
                for (int j = 0; j < 12; j++) {
                    ulonglong2 hh = hd2[j];
                    aX0 = ffma2(hh.x, wX[2 * j], aX0);
                    aX1 = ffma2(hh.y, wX[2 * j + 1], aX1);
                    aY0 = ffma2(hh.x, wY[2 * j], aY0);
                    aY1 = ffma2(hh.y, wY[2 * j + 1], aY1);
                }
                aX0 = add2(aX0, aX1); aY0 = add2(aY0, aY1);
                float x0, x1, y0, y1;
                unpack2(aX0, x0, x1); unpack2(aY0, y0, y1);
                xwout[(size_t)t * 96 + tid] = pack2(x0 + x1, y0 + y1);
            }
            BARS(1, 128);
        }
    } else {
        const int lane = tid - 96;
        int avail = 0, filled = 0;
        while (avail < 48) avail = ld_acq(upcnt);
        {
            int lim = imin(avail, 64);
            for (int r = 0; r < lim; r++) {
                const float* src = hin + (size_t)r * HL;
                sm->h[r & 63][lane] = src[lane];
                if (lane < 16) sm->h[r & 63][32 + lane] = src[32 + lane];
            }
            filled = lim;
        }
        __syncthreads();

        for (int W = 0; W < S_LEN; W += 16) {
            if (lane == 0) st_rel(mycnt, W + 8);       // half-window publish
            int must = imin(W + 48, S_LEN);
            if (filled < must) { while (avail < must) avail = ld_acq(upcnt); }
            else if (filled < S_LEN) { int a = ld_acq(upcnt); if (a > avail) avail = a; }
            int lim = imin(imin(W + 64, S_LEN), avail);
            for (int r = filled; r < lim; r++) {
                const float* src = hin + (size_t)r * HL;
                sm->h[r & 63][lane] = src[lane];
                if (lane < 16) sm->h[r & 63][32 + lane] = src[32 + lane];
            }
            filled = lim;
            BARS(1, 128);
            if (lane == 0) st_rel(mycnt, W + 16);
        }
    }
}

// ---------------- RNN0: 48 -> 24, slack loader ----------------
__device__ void rnn0_stage(unsigned char* smem_raw,
                           const float* __restrict__ Wih, const float* __restrict__ Whh,
                           const float* __restrict__ bih, const float* __restrict__ bhh,
                           const float* __restrict__ hin, const int* upcnt,
                           float* __restrict__ rout, int* mycnt)
{
    Rnn0Smem* sm = reinterpret_cast<Rnn0Smem*>(smem_raw);
    const int tid = threadIdx.x;
    const int wid = tid >> 5, lane = tid & 31;
    if (tid < 24) sm->hb[0][tid] = 0.f;

    if (wid == 0) {                      // recurrence warp
        float wh[24];
        if (lane < 24) {
#pragma unroll
            for (int k = 0; k < 24; k++) wh[k] = Whh[lane * HR + k];
        }
        __syncthreads();
        BARS(2, 64);                     // xw[0] primed by warp 1
        for (int t = 0; t < S_LEN; t++) {
            if (lane < 24) {
                const float* hp = sm->hb[t & 1];
                float a0 = sm->xw[t & 15][lane], a1 = 0, a2 = 0, a3 = 0;
#pragma unroll
                for (int k = 0; k < 24; k += 4) {
                    a0 += hp[k] * wh[k];         a1 += hp[k + 1] * wh[k + 1];
                    a2 += hp[k + 2] * wh[k + 2]; a3 += hp[k + 3] * wh[k + 3];
                }
                float h = tanhap((a0 + a1) + (a2 + a3));
                sm->hb[(t + 1) & 1][lane] = h;
                rout[(size_t)t * HR + lane] = h;
            }
            BARS(2, 64);
            if ((t & 15) == 15) BARS(1, 96);
        }
    } else if (wid == 1) {               // input-projection warp (one step ahead)
        float wi[48], bsum = 0.f;
        if (lane < 24) {
#pragma unroll
            for (int k = 0; k < 48; k++) wi[k] = Wih[lane * HL + k];
            bsum = bih[lane] + bhh[lane];
        }
        __syncthreads();
        if (lane < 24) {                 // prime xw[0]
            const float* hrow = sm->hin[0];
            float a0 = bsum, a1 = 0, a2 = 0, a3 = 0;
#pragma unroll
            for (int k = 0; k < 48; k += 4) {
                a0 += hrow[k] * wi[k];         a1 += hrow[k + 1] * wi[k + 1];
                a2 += hrow[k + 2] * wi[k + 2]; a3 += hrow[k + 3] * wi[k + 3];
            }
            sm->xw[0][lane] = (a0 + a1) + (a2 + a3);
        }
        BARS(2, 64);
        for (int t = 0; t < S_LEN; t++) {
            int tt = t + 1;
            if (tt < S_LEN && lane < 24) {
                const float* hrow = sm->hin[tt & 63];
                float a0 = bsum, a1 = 0, a2 = 0, a3 = 0;
#pragma unroll
                for (int k = 0; k < 48; k += 4) {
                    a0 += hrow[k] * wi[k];         a1 += hrow[k + 1] * wi[k + 1];
                    a2 += hrow[k + 2] * wi[k + 2]; a3 += hrow[k + 3] * wi[k + 3];
                }
                sm->xw[tt & 15][lane] = (a0 + a1) + (a2 + a3);
            }
            BARS(2, 64);
            if ((t & 15) == 15) BARS(1, 96);
        }
    } else if (wid == 3) {               // slack loader
        int avail = 0, filled = 0;
        while (avail < 48) avail = ld_acq(upcnt);
        {
            int lim = imin(avail, 64);
            for (int r = 0; r < lim; r++) {
                const float* src = hin + (size_t)r * HL;
                sm->hin[r & 63][lane] = src[lane];
                if (lane < 16) sm->hin[r & 63][32 + lane] = src[32 + lane];
            }
            filled = lim;
        }
        __syncthreads();
        for (int W = 0; W < S_LEN; W += 16) {
            if (lane == 0) st_rel(mycnt, W + 8);       // half-window publish
            int must = imin(W + 48, S_LEN);
            if (filled < must) { while (avail < must) avail = ld_acq(upcnt); }
            else if (filled < S_LEN) { int a = ld_acq(upcnt); if (a > avail) avail = a; }
            int lim = imin(imin(W + 64, S_LEN), avail);
            for (int r = filled; r < lim; r++) {
                const float* src = hin + (size_t)r * HL;
                sm->hin[r & 63][lane] = src[lane];
                if (lane < 16) sm->hin[r & 63][32 + lane] = src[32 + lane];
            }
            filled = lim;
            BARS(1, 96);
            if (lane == 0) st_rel(mycnt, W + 16);
        }
    } else {                             // warp 2 idle
        __syncthreads();
    }
}

// ---------------- RNN1 + relu + fc4 -> out, slack loader ----------------
__device__ void rnn1_stage(unsigned char* smem_raw,
                           const float* __restrict__ Wih, const float* __restrict__ Whh,
                           const float* __restrict__ bih, const float* __restrict__ bhh,
                           const float* __restrict__ rin, const int* upcnt,
                           const float* __restrict__ fc4W, const float* __restrict__ fc4b,
                           float* __restrict__ out)
{
    Rnn1Smem* sm = reinterpret_cast<Rnn1Smem*>(smem_raw);
    const int tid = threadIdx.x;
    const int wid = tid >> 5, lane = tid & 31;
    if (tid < 24) sm->hb[0][tid] = 0.f;

    if (wid == 0) {                      // recurrence + fc4
        float wh[24], wf[24], bf = 0.f;
        if (lane < 24) {
#pragma unroll
            for (int k = 0; k < 24; k++) wh[k] = Whh[lane * HR + k];
        }
        if (lane == 24 || lane == 25) {
#pragma unroll
            for (int k = 0; k < 24; k++) wf[k] = fc4W[(lane - 24) * HR + k];
            bf = fc4b[lane - 24];
        }
        __syncthreads();
        BARS(2, 64);
        for (int t = 0; t < S_LEN; t++) {
            if (lane < 24) {
                const float* hp = sm->hb[t & 1];
                float a0 = sm->xw[t & 15][lane], a1 = 0, a2 = 0, a3 = 0;
#pragma unroll
                for (int k = 0; k < 24; k += 4) {
                    a0 += hp[k] * wh[k];         a1 += hp[k + 1] * wh[k + 1];
                    a2 += hp[k + 2] * wh[k + 2]; a3 += hp[k + 3] * wh[k + 3];
                }
                float h = tanhap((a0 + a1) + (a2 + a3));
                sm->hb[(t + 1) & 1][lane] = h;
            }
            __syncwarp();
            if (lane == 24 || lane == 25) {
                const float* hc = sm->hb[(t + 1) & 1];
                float a0 = bf, a1 = 0, a2 = 0, a3 = 0;
#pragma unroll
                for (int k = 0; k < 24; k += 4) {
                    a0 += fmaxf(hc[k], 0.f) * wf[k];
                    a1 += fmaxf(hc[k + 1], 0.f) * wf[k + 1];
                    a2 += fmaxf(hc[k + 2], 0.f) * wf[k + 2];
                    a3 += fmaxf(hc[k + 3], 0.f) * wf[k + 3];
                }
                out[(size_t)t * 2 + (lane - 24)] = (a0 + a1) + (a2 + a3);
            }
            BARS(2, 64);
            if ((t & 15) == 15) BARS(1, 96);
        }
    } else if (wid == 1) {               // input projection one step ahead
        float wi[24], bsum = 0.f;
        if (lane < 24) {
#pragma unroll
            for (int k = 0; k < 24; k++) wi[k] = Wih[lane * HR + k];
            bsum = bih[lane] + bhh[lane];
        }
        __syncthreads();
        if (lane < 24) {
            const float* hrow = sm->rin[0];
            float a0 = bsum, a1 = 0, a2 = 0, a3 = 0;
#pragma unroll
            for (int k = 0; k < 24; k += 4) {
                a0 += hrow[k] * wi[k];         a1 += hrow[k + 1] * wi[k + 1];
                a2 += hrow[k + 2] * wi[k + 2]; a3 += hrow[k + 3] * wi[k + 3];
            }
            sm->xw[0][lane] = (a0 + a1) + (a2 + a3);
        }
        BARS(2, 64);
        for (int t = 0; t < S_LEN; t++) {
            int tt = t + 1;
            if (tt < S_LEN && lane < 24) {
                const float* hrow = sm->rin[tt & 63];
                float a0 = bsum, a1 = 0, a2 = 0, a3 = 0;
#pragma unroll
                for (int k = 0; k < 24; k += 4) {
                    a0 += hrow[k] * wi[k];         a1 += hrow[k + 1] * wi[k + 1];
                    a2 += hrow[k + 2] * wi[k + 2]; a3 += hrow[k + 3] * wi[k + 3];
                }
                sm->xw[tt & 15][lane] = (a0 + a1) + (a2 + a3);
            }
            BARS(2, 64);
            if ((t & 15) == 15) BARS(1, 96);
        }
    } else if (wid == 3) {               // slack loader
        int avail = 0, filled = 0;
        while (avail < 48) avail = ld_acq(upcnt);
        {
            int lim = imin(avail, 64);
            for (int r = 0; r < lim; r++) {
                if (lane < 24) sm->rin[r & 63][lane] = rin[(size_t)r * HR + lane];
            }
            filled = lim;
        }
        __syncthreads();
        for (int W = 0; W < S_LEN; W += 16) {
            int must = imin(W + 48, S_LEN);
            if (filled < must) { while (avail < must) avail = ld_acq(upcnt); }
            else if (filled < S_LEN) { int a = ld_acq(upcnt); if (a > avail) avail = a; }
            int lim = imin(imin(W + 64, S_LEN), avail);
            for (int r = filled; r < lim; r++) {
                if (lane < 24) sm->rin[r & 63][lane] = rin[(size_t)r * HR + lane];
            }
            filled = lim;
            BARS(1, 96);
        }
    } else {
        __syncthreads();
    }
}

// ---------------- pipeline dispatcher ----------------
__global__ void __launch_bounds__(128, 1) pipe_kernel(
    const float* lstm0_Whh,
    const float* lstmr_Wih, const float* lstmr_Whh,
    const float* lstmr_bih, const float* lstmr_bhh,
    const float* rnn0_Wih, const float* rnn0_Whh,
    const float* rnn0_bih, const float* rnn0_bhh,
    const float* rnn1_Wih, const float* rnn1_Whh,
    const float* rnn1_bih, const float* rnn1_bhh,
    const float* fc4W, const float* fc4b,
    float* out)
{
    extern __shared__ __align__(16) unsigned char smem[];
    const int b = blockIdx.x;
    if (b == 0) {
        lstm_rec(smem, lstm0_Whh, g_xw0, 0, g_hb[0], &g_cnt[0 * 32]);
    } else if (b <= 8) {
        int l = (b - 1) / 2;
        if ((b & 1) == 1) {
            xw_stage(smem,
                     lstmr_Wih + (size_t)l * 192 * HL,
                     lstmr_bih + (size_t)l * 192,
                     lstmr_bhh + (size_t)l * 192,
                     g_hb[l], &g_cnt[(2 * l) * 32], g_xwb[l], &g_cnt[(2 * l + 1) * 32]);
        } else {
            lstm_rec(smem,
                     lstmr_Whh + (size_t)l * 192 * HL,
                     g_xwb[l], &g_cnt[(2 * l + 1) * 32], g_hb[l + 1], &g_cnt[(2 * l + 2) * 32]);
        }
    } else if (b == 9) {
        rnn0_stage(smem, rnn0_Wih, rnn0_Whh, rnn0_bih, rnn0_bhh,
                   g_hb[4], &g_cnt[8 * 32], g_r0, &g_cnt[9 * 32]);
    } else {
        rnn1_stage(smem, rnn1_Wih, rnn1_Whh, rnn1_bih, rnn1_bhh,
                   g_r0, &g_cnt[9 * 32], fc4W, fc4b, out);
    }
}

extern "C" void kernel_launch(void* const* d_in, const int* in_sizes, int n_in,
                              void* d_out, int out_size) {
    const float* x         = (const float*)d_in[0];
    const float* fc1_W     = (const float*)d_in[1];
    const float* fc1_b     = (const float*)d_in[2];
    const float* fc2_W     = (const float*)d_in[3];
    const float* fc2_b     = (const float*)d_in[4];
    const float* lstm0_Wih = (const float*)d_in[5];
    const float* lstm0_Whh = (const float*)d_in[6];
    const float* lstm0_bih = (const float*)d_in[7];
    const float* lstm0_bhh = (const float*)d_in[8];
    const float* lstmr_Wih = (const float*)d_in[9];
    const float* lstmr_Whh = (const float*)d_in[10];
    const float* lstmr_bih = (const float*)d_in[11];
    const float* lstmr_bhh = (const float*)d_in[12];
    const float* rnn0_Wih  = (const float*)d_in[13];
    const float* rnn0_Whh  = (const float*)d_in[14];
    const float* rnn0_bih  = (const float*)d_in[15];
    const float* rnn0_bhh  = (const float*)d_in[16];
    const float* rnn1_Wih  = (const float*)d_in[17];
    const float* rnn1_Whh  = (const float*)d_in[18];
    const float* rnn1_bih  = (const float*)d_in[19];
    const float* rnn1_bhh  = (const float*)d_in[20];
    const float* fc4_W     = (const float*)d_in[21];
    const float* fc4_b     = (const float*)d_in[22];
    float* out = (float*)d_out;

    static int smem_set = 0;
    if (!smem_set) {
        cudaFuncSetAttribute(pipe_kernel, cudaFuncAttributeMaxDynamicSharedMemorySize,
                             PIPE_SMEM_BYTES);
        smem_set = 1;
    }

    front_kernel<<<S_LEN / 128, 128>>>(x, fc1_W, fc1_b, fc2_W, fc2_b,
                                       lstm0_Wih, lstm0_bih, lstm0_bhh);
    pipe_kernel<<<11, 128, PIPE_SMEM_BYTES>>>(lstm0_Whh,
                             lstmr_Wih, lstmr_Whh, lstmr_bih, lstmr_bhh,
                             rnn0_Wih, rnn0_Whh, rnn0_bih, rnn0_bhh,
                             rnn1_Wih, rnn1_Whh, rnn1_bih, rnn1_bhh,
                             fc4_W, fc4_b, out);
}

// round 17
// speedup vs baseline: 1.0039x; 1.0039x over previous
#include <cuda_runtime.h>

#define S_LEN 16384
#define HL 48
#define HR 24

typedef unsigned long long u64;

__device__ u64   g_xw0[(size_t)S_LEN * 96];       // permuted, PRE-SCALED packed gate pairs
__device__ u64   g_xwb[4][(size_t)S_LEN * 96];
__device__ float g_hb[5][(size_t)S_LEN * HL];
__device__ float g_r0[(size_t)S_LEN * HR];
__device__ int   g_cnt[16 * 32];                  // padded: one counter per 128B

#define BARS(id, cnt) asm volatile("bar.sync %0, %1;" :: "r"(id), "r"(cnt) : "memory")

__device__ __forceinline__ int imin(int a, int b) { return a < b ? a : b; }

__device__ __forceinline__ u64 pack2(float x, float y) {
    u64 r; asm("mov.b64 %0, {%1, %2};" : "=l"(r) : "f"(x), "f"(y)); return r;
}
__device__ __forceinline__ void unpack2(u64 v, float &x, float &y) {
    asm("mov.b64 {%0, %1}, %2;" : "=f"(x), "=f"(y) : "l"(v));
}
__device__ __forceinline__ u64 ffma2(u64 a, u64 b, u64 c) {
    u64 d; asm("fma.rn.f32x2 %0, %1, %2, %3;" : "=l"(d) : "l"(a), "l"(b), "l"(c)); return d;
}
__device__ __forceinline__ u64 add2(u64 a, u64 b) {
    u64 d; asm("add.rn.f32x2 %0, %1, %2;" : "=l"(d) : "l"(a), "l"(b)); return d;
}
__device__ __forceinline__ int ld_acq(const int *p) {
    int v; asm volatile("ld.acquire.gpu.global.b32 %0, [%1];" : "=r"(v) : "l"(p)); return v;
}
__device__ __forceinline__ void st_rel(int *p, int v) {
    asm volatile("st.release.gpu.global.b32 [%0], %1;" :: "l"(p), "r"(v));
}
__device__ __forceinline__ float tanhap(float x) {
    float y; asm("tanh.approx.f32 %0, %1;" : "=f"(y) : "f"(x)); return y;
}
// gate-pair permutation: thread p owns rows (rX, rY) of the 192-row gate matrix.
__device__ __forceinline__ void rowpair(int p, int &rX, int &rY) {
    int w = p >> 5, l = p & 31;
    int m = 16 * w + (l & 15);
    if (l < 16) { rX = m;      rY = 96 + m;  }
    else        { rX = 48 + m; rY = 144 + m; }
}
// pre-scale per gate row: sigmoid rows (i,f,o) carry 0.5; tanh rows (g) carry 1.0
__device__ __forceinline__ float rowscale(int r) {
    return (r >= 96 && r < 144) ? 1.f : 0.5f;
}

// ------------------- shared memory overlays (dynamic) -------------------
struct LstmSmem { u64 xw[64][96]; float hb[2][48]; };
struct XwSmem   { float h[64][48]; };
struct Rnn0Smem { float hin[64][48]; float xw[16][24]; float hb[2][24]; };
struct Rnn1Smem { float rin[64][24]; float xw[16][24]; float hb[2][24]; };
#define PIPE_SMEM_BYTES (sizeof(LstmSmem) + 128)

// ---------------- front: fc1 -> relu -> fc2 -> relu -> permuted scaled xw0 ----------------
__global__ void __launch_bounds__(128) front_kernel(
    const float* __restrict__ x,
    const float* __restrict__ fc1W, const float* __restrict__ fc1b,
    const float* __restrict__ fc2W, const float* __restrict__ fc2b,
    const float* __restrict__ Wih0,
    const float* __restrict__ bih0, const float* __restrict__ bhh0)
{
    __shared__ float s1W[120], s1b[20], s2W[400], s2b[20], s0W[3840], s0b[192];
    const int tid = threadIdx.x;
    for (int i = tid; i < 120; i += 128) s1W[i] = fc1W[i];
    for (int i = tid; i < 400; i += 128) s2W[i] = fc2W[i];
    for (int i = tid; i < 3840; i += 128) s0W[i] = Wih0[i] * rowscale(i / 20);
    for (int i = tid; i < 192; i += 128) s0b[i] = (bih0[i] + bhh0[i]) * rowscale(i);
    if (tid < 20) { s1b[tid] = fc1b[tid]; s2b[tid] = fc2b[tid]; }
    if (blockIdx.x == 0 && tid < 16) g_cnt[tid * 32] = 0;
    __syncthreads();

    const int t = blockIdx.x * 128 + tid;
    float xin[6];
#pragma unroll
    for (int i = 0; i < 6; i++) xin[i] = x[t * 6 + i];
    float h1[20];
#pragma unroll
    for (int j = 0; j < 20; j++) {
        float s = s1b[j];
#pragma unroll
        for (int i = 0; i < 6; i++) s += xin[i] * s1W[j * 6 + i];
        h1[j] = fmaxf(s, 0.f);
    }
    float h2[20];
#pragma unroll
    for (int j = 0; j < 20; j++) {
        float s = s2b[j];
#pragma unroll
        for (int i = 0; i < 20; i++) s += h1[i] * s2W[j * 20 + i];
        h2[j] = fmaxf(s, 0.f);
    }
    for (int p = 0; p < 96; p++) {
        int rX, rY; rowpair(p, rX, rY);
        float sX = s0b[rX], sY = s0b[rY];
#pragma unroll
        for (int k = 0; k < 20; k++) {
            float hv = h2[k];
            sX += hv * s0W[rX * 20 + k];
            sY += hv * s0W[rY * 20 + k];
        }
        g_xw0[(size_t)t * 96 + p] = pack2(sX, sY);
    }
}

// ---------------- LSTM recurrence: slack loader (ring 64), shfl gate exchange ----------------
__device__ void lstm_rec(unsigned char* smem_raw,
                         const float* __restrict__ Whh, const u64* __restrict__ xwsrc,
                         const int* upcnt, float* __restrict__ hout, int* mycnt)
{
    LstmSmem* sm = reinterpret_cast<LstmSmem*>(smem_raw);
    const int tid = threadIdx.x;

    if (tid < 96) {
        u64 wX[24], wY[24];
        int rX, rY; rowpair(tid, rX, rY);
        const float scX = rowscale(rX), scY = rowscale(rY);
        const float* r0 = Whh + rX * HL;
        const float* r1 = Whh + rY * HL;
#pragma unroll
        for (int j = 0; j < 24; j++) {
            wX[j] = pack2(r0[2 * j] * scX, r0[2 * j + 1] * scX);
            wY[j] = pack2(r1[2 * j] * scY, r1[2 * j + 1] * scY);
        }
        const int m = 16 * (tid >> 5) + (tid & 15);
        const bool isA = (tid & 31) < 16;
        const float avm = isA ? 1.f : 0.5f;
        const float avb = isA ? 0.f : 0.5f;
        float c = 0.f;
        if (tid < 48) sm->hb[0][tid] = 0.f;
        __syncthreads();

        u64 xw_cur = sm->xw[0][tid];
        for (int t = 0; t < S_LEN; t++) {
            float xwX, xwY; unpack2(xw_cur, xwX, xwY);
            const ulonglong2* hd2 = (const ulonglong2*)sm->hb[t & 1];
            // fold xw into accumulator init (off-chain) instead of post-reduce add
            u64 aX0 = pack2(xwX, 0.f), aX1 = 0, aY0 = pack2(xwY, 0.f), aY1 = 0;
#pragma unroll
            for (int j = 0; j < 12; j++) {
                ulonglong2 hh = hd2[j];
                aX0 = ffma2(hh.x, wX[2 * j], aX0);
                aX1 = ffma2(hh.y, wX[2 * j + 1], aX1);
                aY0 = ffma2(hh.x, wY[2 * j], aY0);
                aY1 = ffma2(hh.y, wY[2 * j + 1], aY1);
            }
            aX0 = add2(aX0, aX1); aY0 = add2(aY0, aY1);
            float x0, x1, y0, y1;
            unpack2(aX0, x0, x1); unpack2(aY0, y0, y1);
            float gx = x0 + x1;
            float gy = y0 + y1;
            float ax = fmaf(0.5f, tanhap(gx), 0.5f);   // sigmoid (i / f); 0.5 folded into W
            float ay = fmaf(avm, tanhap(gy), avb);     // A: tanh(g)  B: sigmoid(o)
            float fv = __shfl_down_sync(0xffffffffu, ax, 16);
            float ov = __shfl_down_sync(0xffffffffu, ay, 16);
            if (isA) {
                c = fmaf(fv, c, ax * ay);
                float h = ov * tanhap(c);
                sm->hb[(t + 1) & 1][m] = h;
                hout[(size_t)t * HL + m] = h;
            }
            if ((t & 15) != 15) {
                u64 xw_nxt = sm->xw[(t + 1) & 63][tid];   // row t+1 < W+32: filled
                BARS(2, 96);
                xw_cur = xw_nxt;
            } else {
                BARS(1, 128);
                xw_cur = sm->xw[(t + 1) & 63][tid];       // first row of next window
            }
        }
    } else {
        const int lane = tid - 96;
        int avail = 0, filled = 0;
        if (upcnt) { while (avail < 48) avail = ld_acq(upcnt); }
        else avail = S_LEN;
        {
            int lim = imin(avail, 64);
            for (int r = 0; r < lim; r++) {
                const u64* src = xwsrc + (size_t)r * 96;
                u64* dst = sm->xw[r & 63];
                dst[lane] = src[lane]; dst[32 + lane] = src[32 + lane]; dst[64 + lane] = src[64 + lane];
            }
            filled = lim;
        }
        __syncthreads();

        for (int W = 0; W < S_LEN; W += 16) {
            int must = imin(W + 48, S_LEN);
            if (filled < must) {
                if (upcnt) { while (avail < must) avail = ld_acq(upcnt); }
                else avail = S_LEN;
            } else if (upcnt && filled < S_LEN) {
                int a = ld_acq(upcnt); if (a > avail) avail = a;   // opportunistic refresh
            }
            int lim = imin(imin(W + 64, S_LEN), avail);
            for (int r = filled; r < lim; r++) {
                const u64* src = xwsrc + (size_t)r * 96;
                u64* dst = sm->xw[r & 63];
                dst[lane] = src[lane]; dst[32 + lane] = src[32 + lane]; dst[64 + lane] = src[64 + lane];
            }
            filled = lim;
            BARS(1, 128);
            if (lane == 0 && mycnt) st_rel(mycnt, W + 16);
        }
    }
}

// ---------------- feedforward xw stage (LSTM layers 1..4), slack loader ----------------
__device__ void xw_stage(unsigned char* smem_raw,
                         const float* __restrict__ Wih, const float* __restrict__ bih,
                         const float* __restrict__ bhh, const float* __restrict__ hin,
                         const int* upcnt, u64* __restrict__ xwout, int* mycnt)
{
    XwSmem* sm = reinterpret_cast<XwSmem*>(smem_raw);
    const int tid = threadIdx.x;

    if (tid < 96) {
        u64 wX[24], wY[24];
        int rX, rY; rowpair(tid, rX, rY);
        const float scX = rowscale(rX), scY = rowscale(rY);
        const float* r0 = Wih + rX * HL;
        const float* r1 = Wih + rY * HL;
#pragma unroll
        for (int j = 0; j < 24; j++) {
            wX[j] = pack2(r0[2 * j] * scX, r0[2 * j + 1] * scX);
            wY[j] = pack2(r1[2 * j] * scY, r1[2 * j + 1] * scY);
        }
        const float biasX = (bih[rX] + bhh[rX]) * scX;
        const float biasY = (bih[rY] + bhh[rY]) * scY;
        const u64 binitX = pack2(biasX, 0.f);
        const u64 binitY = pack2(biasY, 0.f);
        __syncthreads();

        for (int W = 0; W < S_LEN; W += 16) {
#pragma unroll 2
            for (int s = 0; s < 16; s++) {
                int t = W + s;
                const ulonglong2* hd2 = (const ulonglong2*)sm->h[t & 63];
                u64 aX0 = binitX, aX1 = 0, aY0 = binitY, aY1 = 0;
#pragma unroll
                for (int j = 0; j < 12; j++) {
                    ulonglong2 hh = hd2[j];
                    aX0 = ffma2(hh.x, wX[2 * j], aX0);
                    aX1 = ffma2(hh.y, wX[2 * j + 1], aX1);
                    aY0 = ffma2(hh.x, wY[2 * j], aY0);
                    aY1 = ffma2(hh.y, wY[2 * j + 1], aY1);
                }
                aX0 = add2(aX0, aX1); aY0 = add2(aY0, aY1);
                float x0, x1, y0, y1;
                unpack2(aX0, x0, x1); unpack2(aY0, y0, y1);
                xwout[(size_t)t * 96 + tid] = pack2(x0 + x1, y0 + y1);
            }
            BARS(1, 128);
        }
    } else {
        const int lane = tid - 96;
        int avail = 0, filled = 0;
        while (avail < 48) avail = ld_acq(upcnt);
        {
            int lim = imin(avail, 64);
            for (int r = 0; r < lim; r++) {
                const float* src = hin + (size_t)r * HL;
                sm->h[r & 63][lane] = src[lane];
                if (lane < 16) sm->h[r & 63][32 + lane] = src[32 + lane];
            }
            filled = lim;
        }
        __syncthreads();

        for (int W = 0; W < S_LEN; W += 16) {
            int must = imin(W + 48, S_LEN);
            if (filled < must) { while (avail < must) avail = ld_acq(upcnt); }
            else if (filled < S_LEN) { int a = ld_acq(upcnt); if (a > avail) avail = a; }
            int lim = imin(imin(W + 64, S_LEN), avail);
            for (int r = filled; r < lim; r++) {
                const float* src = hin + (size_t)r * HL;
                sm->h[r & 63][lane] = src[lane];
                if (lane < 16) sm->h[r & 63][32 + lane] = src[32 + lane];
            }
            filled = lim;
            BARS(1, 128);
            if (lane == 0) st_rel(mycnt, W + 16);
        }
    }
}

// ---------------- RNN0: 48 -> 24, slack loader ----------------
__device__ void rnn0_stage(unsigned char* smem_raw,
                           const float* __restrict__ Wih, const float* __restrict__ Whh,
                           const float* __restrict__ bih, const float* __restrict__ bhh,
                           const float* __restrict__ hin, const int* upcnt,
                           float* __restrict__ rout, int* mycnt)
{
    Rnn0Smem* sm = reinterpret_cast<Rnn0Smem*>(smem_raw);
    const int tid = threadIdx.x;
    const int wid = tid >> 5, lane = tid & 31;
    if (tid < 24) sm->hb[0][tid] = 0.f;

    if (wid == 0) {                      // recurrence warp
        float wh[24];
        if (lane < 24) {
#pragma unroll
            for (int k = 0; k < 24; k++) wh[k] = Whh[lane * HR + k];
        }
        __syncthreads();
        BARS(2, 64);                     // xw[0] primed by warp 1
        for (int t = 0; t < S_LEN; t++) {
            if (lane < 24) {
                const float* hp = sm->hb[t & 1];
                float a0 = sm->xw[t & 15][lane], a1 = 0, a2 = 0, a3 = 0;
#pragma unroll
                for (int k = 0; k < 24; k += 4) {
                    a0 += hp[k] * wh[k];         a1 += hp[k + 1] * wh[k + 1];
                    a2 += hp[k + 2] * wh[k + 2]; a3 += hp[k + 3] * wh[k + 3];
                }
                float h = tanhap((a0 + a1) + (a2 + a3));
                sm->hb[(t + 1) & 1][lane] = h;
                rout[(size_t)t * HR + lane] = h;
            }
            BARS(2, 64);
            if ((t & 15) == 15) BARS(1, 96);
        }
    } else if (wid == 1) {               // input-projection warp (one step ahead)
        float wi[48], bsum = 0.f;
        if (lane < 24) {
#pragma unroll
            for (int k = 0; k < 48; k++) wi[k] = Wih[lane * HL + k];
            bsum = bih[lane] + bhh[lane];
        }
        __syncthreads();
        if (lane < 24) {                 // prime xw[0]
            const float* hrow = sm->hin[0];
            float a0 = bsum, a1 = 0, a2 = 0, a3 = 0;
#pragma unroll
            for (int k = 0; k < 48; k += 4) {
                a0 += hrow[k] * wi[k];         a1 += hrow[k + 1] * wi[k + 1];
                a2 += hrow[k + 2] * wi[k + 2]; a3 += hrow[k + 3] * wi[k + 3];
            }
            sm->xw[0][lane] = (a0 + a1) + (a2 + a3);
        }
        BARS(2, 64);
        for (int t = 0; t < S_LEN; t++) {
            int tt = t + 1;
            if (tt < S_LEN && lane < 24) {
                const float* hrow = sm->hin[tt & 63];
                float a0 = bsum, a1 = 0, a2 = 0, a3 = 0;
#pragma unroll
                for (int k = 0; k < 48; k += 4) {
                    a0 += hrow[k] * wi[k];         a1 += hrow[k + 1] * wi[k + 1];
                    a2 += hrow[k + 2] * wi[k + 2]; a3 += hrow[k + 3] * wi[k + 3];
                }
                sm->xw[tt & 15][lane] = (a0 + a1) + (a2 + a3);
            }
            BARS(2, 64);
            if ((t & 15) == 15) BARS(1, 96);
        }
    } else if (wid == 3) {               // slack loader
        int avail = 0, filled = 0;
        while (avail < 48) avail = ld_acq(upcnt);
        {
            int lim = imin(avail, 64);
            for (int r = 0; r < lim; r++) {
                const float* src = hin + (size_t)r * HL;
                sm->hin[r & 63][lane] = src[lane];
                if (lane < 16) sm->hin[r & 63][32 + lane] = src[32 + lane];
            }
            filled = lim;
        }
        __syncthreads();
        for (int W = 0; W < S_LEN; W += 16) {
            int must = imin(W + 48, S_LEN);
            if (filled < must) { while (avail < must) avail = ld_acq(upcnt); }
            else if (filled < S_LEN) { int a = ld_acq(upcnt); if (a > avail) avail = a; }
            int lim = imin(imin(W + 64, S_LEN), avail);
            for (int r = filled; r < lim; r++) {
                const float* src = hin + (size_t)r * HL;
                sm->hin[r & 63][lane] = src[lane];
                if (lane < 16) sm->hin[r & 63][32 + lane] = src[32 + lane];
            }
            filled = lim;
            BARS(1, 96);
            if (lane == 0) st_rel(mycnt, W + 16);
        }
    } else {                             // warp 2 idle
        __syncthreads();
    }
}

// ---------------- RNN1 + relu + fc4 -> out, slack loader ----------------
__device__ void rnn1_stage(unsigned char* smem_raw,
                           const float* __restrict__ Wih, const float* __restrict__ Whh,
                           const float* __restrict__ bih, const float* __restrict__ bhh,
                           const float* __restrict__ rin, const int* upcnt,
                           const float* __restrict__ fc4W, const float* __restrict__ fc4b,
                           float* __restrict__ out)
{
    Rnn1Smem* sm = reinterpret_cast<Rnn1Smem*>(smem_raw);
    const int tid = threadIdx.x;
    const int wid = tid >> 5, lane = tid & 31;
    if (tid < 24) sm->hb[0][tid] = 0.f;

    if (wid == 0) {                      // recurrence + fc4
        float wh[24], wf[24], bf = 0.f;
        if (lane < 24) {
#pragma unroll
            for (int k = 0; k < 24; k++) wh[k] = Whh[lane * HR + k];
        }
        if (lane == 24 || lane == 25) {
#pragma unroll
            for (int k = 0; k < 24; k++) wf[k] = fc4W[(lane - 24) * HR + k];
            bf = fc4b[lane - 24];
        }
        __syncthreads();
        BARS(2, 64);
        for (int t = 0; t < S_LEN; t++) {
            if (lane < 24) {
                const float* hp = sm->hb[t & 1];
                float a0 = sm->xw[t & 15][lane], a1 = 0, a2 = 0, a3 = 0;
#pragma unroll
                for (int k = 0; k < 24; k += 4) {
                    a0 += hp[k] * wh[k];         a1 += hp[k + 1] * wh[k + 1];
                    a2 += hp[k + 2] * wh[k + 2]; a3 += hp[k + 3] * wh[k + 3];
                }
                float h = tanhap((a0 + a1) + (a2 + a3));
                sm->hb[(t + 1) & 1][lane] = h;
            }
            __syncwarp();
            if (lane == 24 || lane == 25) {
                const float* hc = sm->hb[(t + 1) & 1];
                float a0 = bf, a1 = 0, a2 = 0, a3 = 0;
#pragma unroll
                for (int k = 0; k < 24; k += 4) {
                    a0 += fmaxf(hc[k], 0.f) * wf[k];
                    a1 += fmaxf(hc[k + 1], 0.f) * wf[k + 1];
                    a2 += fmaxf(hc[k + 2], 0.f) * wf[k + 2];
                    a3 += fmaxf(hc[k + 3], 0.f) * wf[k + 3];
                }
                out[(size_t)t * 2 + (lane - 24)] = (a0 + a1) + (a2 + a3);
            }
            BARS(2, 64);
            if ((t & 15) == 15) BARS(1, 96);
        }
    } else if (wid == 1) {               // input projection one step ahead
        float wi[24], bsum = 0.f;
        if (lane < 24) {
#pragma unroll
            for (int k = 0; k < 24; k++) wi[k] = Wih[lane * HR + k];
            bsum = bih[lane] + bhh[lane];
        }
        __syncthreads();
        if (lane < 24) {
            const float* hrow = sm->rin[0];
            float a0 = bsum, a1 = 0, a2 = 0, a3 = 0;
#pragma unroll
            for (int k = 0; k < 24; k += 4) {
                a0 += hrow[k] * wi[k];         a1 += hrow[k + 1] * wi[k + 1];
                a2 += hrow[k + 2] * wi[k + 2]; a3 += hrow[k + 3] * wi[k + 3];
            }
            sm->xw[0][lane] = (a0 + a1) + (a2 + a3);
        }
        BARS(2, 64);
        for (int t = 0; t < S_LEN; t++) {
            int tt = t + 1;
            if (tt < S_LEN && lane < 24) {
                const float* hrow = sm->rin[tt & 63];
                float a0 = bsum, a1 = 0, a2 = 0, a3 = 0;
#pragma unroll
                for (int k = 0; k < 24; k += 4) {
                    a0 += hrow[k] * wi[k];         a1 += hrow[k + 1] * wi[k + 1];
                    a2 += hrow[k + 2] * wi[k + 2]; a3 += hrow[k + 3] * wi[k + 3];
                }
                sm->xw[tt & 15][lane] = (a0 + a1) + (a2 + a3);
            }
            BARS(2, 64);
            if ((t & 15) == 15) BARS(1, 96);
        }
    } else if (wid == 3) {               // slack loader
        int avail = 0, filled = 0;
        while (avail < 48) avail = ld_acq(upcnt);
        {
            int lim = imin(avail, 64);
            for (int r = 0; r < lim; r++) {
                if (lane < 24) sm->rin[r & 63][lane] = rin[(size_t)r * HR + lane];
            }
            filled = lim;
        }
        __syncthreads();
        for (int W = 0; W < S_LEN; W += 16) {
            int must = imin(W + 48, S_LEN);
            if (filled < must) { while (avail < must) avail = ld_acq(upcnt); }
            else if (filled < S_LEN) { int a = ld_acq(upcnt); if (a > avail) avail = a; }
            int lim = imin(imin(W + 64, S_LEN), avail);
            for (int r = filled; r < lim; r++) {
                if (lane < 24) sm->rin[r & 63][lane] = rin[(size_t)r * HR + lane];
            }
            filled = lim;
            BARS(1, 96);
        }
    } else {
        __syncthreads();
    }
}

// ---------------- pipeline dispatcher ----------------
__global__ void __launch_bounds__(128, 1) pipe_kernel(
    const float* lstm0_Whh,
    const float* lstmr_Wih, const float* lstmr_Whh,
    const float* lstmr_bih, const float* lstmr_bhh,
    const float* rnn0_Wih, const float* rnn0_Whh,
    const float* rnn0_bih, const float* rnn0_bhh,
    const float* rnn1_Wih, const float* rnn1_Whh,
    const float* rnn1_bih, const float* rnn1_bhh,
    const float* fc4W, const float* fc4b,
    float* out)
{
    extern __shared__ __align__(16) unsigned char smem[];
    const int b = blockIdx.x;
    if (b == 0) {
        lstm_rec(smem, lstm0_Whh, g_xw0, 0, g_hb[0], &g_cnt[0 * 32]);
    } else if (b <= 8) {
        int l = (b - 1) / 2;
        if ((b & 1) == 1) {
            xw_stage(smem,
                     lstmr_Wih + (size_t)l * 192 * HL,
                     lstmr_bih + (size_t)l * 192,
                     lstmr_bhh + (size_t)l * 192,
                     g_hb[l], &g_cnt[(2 * l) * 32], g_xwb[l], &g_cnt[(2 * l + 1) * 32]);
        } else {
            lstm_rec(smem,
                     lstmr_Whh + (size_t)l * 192 * HL,
                     g_xwb[l], &g_cnt[(2 * l + 1) * 32], g_hb[l + 1], &g_cnt[(2 * l + 2) * 32]);
        }
    } else if (b == 9) {
        rnn0_stage(smem, rnn0_Wih, rnn0_Whh, rnn0_bih, rnn0_bhh,
                   g_hb[4], &g_cnt[8 * 32], g_r0, &g_cnt[9 * 32]);
    } else {
        rnn1_stage(smem, rnn1_Wih, rnn1_Whh, rnn1_bih, rnn1_bhh,
                   g_r0, &g_cnt[9 * 32], fc4W, fc4b, out);
    }
}

extern "C" void kernel_launch(void* const* d_in, const int* in_sizes, int n_in,
                              void* d_out, int out_size) {
    const float* x         = (const float*)d_in[0];
    const float* fc1_W     = (const float*)d_in[1];
    const float* fc1_b     = (const float*)d_in[2];
    const float* fc2_W     = (const float*)d_in[3];
    const float* fc2_b     = (const float*)d_in[4];
    const float* lstm0_Wih = (const float*)d_in[5];
    const float* lstm0_Whh = (const float*)d_in[6];
    const float* lstm0_bih = (const float*)d_in[7];
    const float* lstm0_bhh = (const float*)d_in[8];
    const float* lstmr_Wih = (const float*)d_in[9];
    const float* lstmr_Whh = (const float*)d_in[10];
    const float* lstmr_bih = (const float*)d_in[11];
    const float* lstmr_bhh = (const float*)d_in[12];
    const float* rnn0_Wih  = (const float*)d_in[13];
    const float* rnn0_Whh  = (const float*)d_in[14];
    const float* rnn0_bih  = (const float*)d_in[15];
    const float* rnn0_bhh  = (const float*)d_in[16];
    const float* rnn1_Wih  = (const float*)d_in[17];
    const float* rnn1_Whh  = (const float*)d_in[18];
    const float* rnn1_bih  = (const float*)d_in[19];
    const float* rnn1_bhh  = (const float*)d_in[20];
    const float* fc4_W     = (const float*)d_in[21];
    const float* fc4_b     = (const float*)d_in[22];
    float* out = (float*)d_out;

    static int smem_set = 0;
    if (!smem_set) {
        cudaFuncSetAttribute(pipe_kernel, cudaFuncAttributeMaxDynamicSharedMemorySize,
                             PIPE_SMEM_BYTES);
        smem_set = 1;
    }

    front_kernel<<<S_LEN / 128, 128>>>(x, fc1_W, fc1_b, fc2_W, fc2_b,
                                       lstm0_Wih, lstm0_bih, lstm0_bhh);
    pipe_kernel<<<11, 128, PIPE_SMEM_BYTES>>>(lstm0_Whh,
                             lstmr_Wih, lstmr_Whh, lstmr_bih, lstmr_bhh,
                             rnn0_Wih, rnn0_Whh, rnn0_bih, rnn0_bhh,
                             rnn1_Wih, rnn1_Whh, rnn1_bih, rnn1_bhh,
                             fc4_W, fc4_b, out);
}